// round 11
// baseline (speedup 1.0000x reference)
#include <cuda_runtime.h>
#include <cuda_bf16.h>
#include <cstdint>
#include <math.h>

#define Bn   2
#define Tn   2048
#define Cn   1024
#define Hn   16
#define HDn  64
#define HD2n 32
#define Mn   (Bn * Tn)          // 4096
#define N3n  (3 * Cn)           // 3072
#define Kn   1024

// ---------------------------------------------------------------------------
// Scratch pool
// ---------------------------------------------------------------------------
#define OFF_QKV   0ull                                   // fp32 [4096][3072]
#define OFF_XH    (OFF_QKV   + 50331648ull)              // bf16 [4096][1024]
#define OFF_XL    (OFF_XH    + 8388608ull)
#define OFF_WQH   (OFF_XL    + 8388608ull)               // bf16 [3072][1024]
#define OFF_WQL   (OFF_WQH   + 6291456ull)
#define OFF_WPH   (OFF_WQL   + 6291456ull)               // bf16 [1024][1024]
#define OFF_WPL   (OFF_WPH   + 2097152ull)
#define OFF_AH    (OFF_WPL   + 2097152ull)               // bf16 [4096][1024]
#define OFF_AL    (OFF_AH    + 8388608ull)
#define OFF_QH    (OFF_AL    + 8388608ull)               // bf16 [32][2048][64]
#define OFF_QL    (OFF_QH    + 8388608ull)
#define OFF_KH    (OFF_QL    + 8388608ull)
#define OFF_KL    (OFF_KH    + 8388608ull)
#define OFF_VH    (OFF_KL    + 8388608ull)               // bf16 [32][64][2048]
#define OFF_VL    (OFF_VH    + 8388608ull)
#define POOL_SZ   (OFF_VL    + 8388608ull)

__device__ __align__(1024) unsigned char g_pool[POOL_SZ];

// ---------------------------------------------------------------------------
// helpers
// ---------------------------------------------------------------------------
#define MMA16816(d, a, b) \
    asm volatile( \
        "mma.sync.aligned.m16n8k16.row.col.f32.bf16.bf16.f32 " \
        "{%0,%1,%2,%3}, {%4,%5,%6,%7}, {%8,%9}, {%0,%1,%2,%3};" \
        : "+f"((d)[0]), "+f"((d)[1]), "+f"((d)[2]), "+f"((d)[3]) \
        : "r"((a)[0]), "r"((a)[1]), "r"((a)[2]), "r"((a)[3]), \
          "r"((b)[0]), "r"((b)[1]))

#define LDSM4(r0, r1, r2, r3, a) \
    asm volatile("ldmatrix.sync.aligned.m8n8.x4.shared.b16 {%0,%1,%2,%3}, [%4];" \
        : "=r"(r0), "=r"(r1), "=r"(r2), "=r"(r3) : "r"(a))

#define CP_ASYNC16(dst, src) \
    asm volatile("cp.async.cg.shared.global [%0], [%1], 16;" \
                 :: "r"(dst), "l"(src) : "memory")
#define CP_COMMIT() asm volatile("cp.async.commit_group;" ::: "memory")

__device__ __forceinline__ uint32_t smem_u32(const void* p) {
    uint32_t a;
    asm("{ .reg .u64 t; cvta.to.shared.u64 t, %1; cvt.u32.u64 %0, t; }"
        : "=r"(a) : "l"(p));
    return a;
}

__device__ __forceinline__ uint32_t pack_bf2(float x, float y) {
    __nv_bfloat162 v = __floats2bfloat162_rn(x, y);
    return *(uint32_t*)&v;
}

// ---------------------------------------------------------------------------
// Split fp32 -> bf16 hi/lo
// ---------------------------------------------------------------------------
__global__ __launch_bounds__(256) void split_kernel(
    const float* __restrict__ in, __nv_bfloat16* __restrict__ h,
    __nv_bfloat16* __restrict__ l, int n)
{
    int i = blockIdx.x * 256 + threadIdx.x;
    if (i < n) {
        float v = in[i];
        __nv_bfloat16 hv = __float2bfloat16(v);
        h[i] = hv;
        l[i] = __float2bfloat16(v - __bfloat162float(hv));
    }
}

// ---------------------------------------------------------------------------
// Transpose + split: W[K][N] fp32 -> Th, Tl [N][K] bf16
// ---------------------------------------------------------------------------
__global__ __launch_bounds__(256) void transpose_split_kernel(
    const float* __restrict__ W, __nv_bfloat16* __restrict__ Th,
    __nv_bfloat16* __restrict__ Tl, int K, int N)
{
    __shared__ float t[32][33];
    int n0 = blockIdx.x * 32, k0 = blockIdx.y * 32;
    int tx = threadIdx.x & 31, ty = threadIdx.x >> 5;
    #pragma unroll
    for (int r = 0; r < 4; r++)
        t[ty + 8 * r][tx] = W[(size_t)(k0 + ty + 8 * r) * N + n0 + tx];
    __syncthreads();
    #pragma unroll
    for (int r = 0; r < 4; r++) {
        float v = t[tx][ty + 8 * r];
        __nv_bfloat16 hv = __float2bfloat16(v);
        size_t o = (size_t)(n0 + ty + 8 * r) * K + k0 + tx;
        Th[o] = hv;
        Tl[o] = __float2bfloat16(v - __bfloat162float(hv));
    }
}

// ---------------------------------------------------------------------------
// bf16x3 GEMM: 3-stage cp.async pipeline, single sync per chunk,
// B-fragment double buffering. 128x128 CTA tile, 8 warps, BK=32.
// ---------------------------------------------------------------------------
#define GSTRIDE  80u
#define GMATB    10240u
#define GSTAGE   40960u
#define GSTAGES  3
#define GEMM_SMEM (GSTAGES * GSTAGE)     // 122880
#define NCHUNK   32

__global__ __launch_bounds__(256) void gemm_bf16x3_kernel(int N,
    const __nv_bfloat16* __restrict__ Ah, const __nv_bfloat16* __restrict__ Al,
    const __nv_bfloat16* __restrict__ Bh, const __nv_bfloat16* __restrict__ Bl,
    const float* __restrict__ bias, float* __restrict__ C)
{
    extern __shared__ unsigned char smem[];
    const uint32_t sb = smem_u32(smem);

    const int tid  = threadIdx.x;
    const int lane = tid & 31;
    const int warp = tid >> 5;
    const int wm   = warp >> 2;
    const int wn   = warp & 3;
    const int g    = lane >> 2;
    const int t    = lane & 3;
    const int brow = blockIdx.y * 128;
    const int bcol = blockIdx.x * 128;

    const uint32_t a_lane = (uint32_t)((lane & 7) + ((lane >> 3) & 1) * 8) * GSTRIDE
                          + (uint32_t)(lane >> 4) * 16u;
    const uint32_t b_lane = (uint32_t)((lane & 7) + ((lane >> 4) & 1) * 8) * GSTRIDE
                          + (uint32_t)((lane >> 3) & 1) * 16u;

    float acc[4][4][4];
    #pragma unroll
    for (int i = 0; i < 4; i++)
        #pragma unroll
        for (int j = 0; j < 4; j++)
            #pragma unroll
            for (int r = 0; r < 4; r++) acc[i][j][r] = 0.f;

    auto load_chunk = [&](int c) {
        const uint32_t base = sb + (uint32_t)(c % GSTAGES) * GSTAGE;
        const int kc = c * 32;
        #pragma unroll
        for (int m = 0; m < 4; m++) {
            const __nv_bfloat16* src = (m == 0) ? Ah : (m == 1) ? Al
                                     : (m == 2) ? Bh : Bl;
            const int rb = (m < 2) ? brow : bcol;
            #pragma unroll
            for (int i = 0; i < 2; i++) {
                int u   = tid + i * 256;
                int row = u >> 2, q = u & 3;
                const __nv_bfloat16* gsrc =
                    src + (size_t)(rb + row) * Kn + kc + q * 8;
                uint32_t dst = base + m * GMATB + row * GSTRIDE + q * 16u;
                CP_ASYNC16(dst, gsrc);
            }
        }
        CP_COMMIT();
    };

    load_chunk(0);
    load_chunk(1);

    for (int c = 0; c < NCHUNK; c++) {
        if (c < NCHUNK - 1)
            asm volatile("cp.async.wait_group 1;" ::: "memory");
        else
            asm volatile("cp.async.wait_group 0;" ::: "memory");
        __syncthreads();
        // stage (c+2)%3 was last read at iteration c-1; safe to overwrite now
        if (c + 2 < NCHUNK) load_chunk(c + 2);

        const uint32_t stg = sb + (uint32_t)(c % GSTAGES) * GSTAGE;

        #pragma unroll
        for (int s = 0; s < 2; s++) {
            const uint32_t kb = s * 32u;
            uint32_t ah[4][4], al[4][4];
            #pragma unroll
            for (int i = 0; i < 4; i++) {
                uint32_t r = stg + (uint32_t)(wm * 64 + i * 16) * GSTRIDE + kb + a_lane;
                LDSM4(ah[i][0], ah[i][1], ah[i][2], ah[i][3], r);
                LDSM4(al[i][0], al[i][1], al[i][2], al[i][3], r + GMATB);
            }
            // B double buffer: bh/bl[pbuf][jj][2]
            uint32_t bh[2][2][2], bl[2][2][2];
            {
                uint32_t r = stg + 2u * GMATB + (uint32_t)(wn * 32) * GSTRIDE + kb + b_lane;
                LDSM4(bh[0][0][0], bh[0][0][1], bh[0][1][0], bh[0][1][1], r);
                LDSM4(bl[0][0][0], bl[0][0][1], bl[0][1][0], bl[0][1][1], r + GMATB);
            }
            #pragma unroll
            for (int p = 0; p < 2; p++) {
                if (p == 0) {
                    // prefetch B for p=1 before p=0's MMAs
                    uint32_t r = stg + 2u * GMATB
                               + (uint32_t)(wn * 32 + 16) * GSTRIDE + kb + b_lane;
                    LDSM4(bh[1][0][0], bh[1][0][1], bh[1][1][0], bh[1][1][1], r);
                    LDSM4(bl[1][0][0], bl[1][0][1], bl[1][1][0], bl[1][1][1], r + GMATB);
                }
                #pragma unroll
                for (int jj = 0; jj < 2; jj++) {
                    const int j = p * 2 + jj;
                    #pragma unroll
                    for (int i = 0; i < 4; i++) MMA16816(acc[i][j], ah[i], bh[p][jj]);
                    #pragma unroll
                    for (int i = 0; i < 4; i++) MMA16816(acc[i][j], ah[i], bl[p][jj]);
                    #pragma unroll
                    for (int i = 0; i < 4; i++) MMA16816(acc[i][j], al[i], bh[p][jj]);
                }
            }
        }
    }

    #pragma unroll
    for (int i = 0; i < 4; i++) {
        const int r0 = brow + wm * 64 + i * 16 + g;
        #pragma unroll
        for (int j = 0; j < 4; j++) {
            const int col = bcol + wn * 32 + j * 8 + t * 2;
            float2 bs = *(const float2*)(bias + col);
            float2 o0, o1;
            o0.x = acc[i][j][0] + bs.x;
            o0.y = acc[i][j][1] + bs.y;
            o1.x = acc[i][j][2] + bs.x;
            o1.y = acc[i][j][3] + bs.y;
            *(float2*)(C + (size_t)r0 * N + col)       = o0;
            *(float2*)(C + (size_t)(r0 + 8) * N + col) = o1;
        }
    }
}

// ---------------------------------------------------------------------------
// Prep A: RoPE + scale(Q) + hi/lo split of Q,K -> [bh][T][64] bf16
// ---------------------------------------------------------------------------
__global__ __launch_bounds__(256) void rope_split_qk_kernel(
    const float* __restrict__ qkv,
    const float* __restrict__ fcos, const float* __restrict__ fsin,
    __nv_bfloat16* __restrict__ Qh, __nv_bfloat16* __restrict__ Ql,
    __nv_bfloat16* __restrict__ Kh, __nv_bfloat16* __restrict__ Kl)
{
    int i = blockIdx.x * 256 + threadIdx.x;
    int d  = i & 31;
    int h  = (i >> 5) & 15;
    int tt = (i >> 9) & 2047;
    int b  = i >> 20;

    float c = fcos[tt * HD2n + d];
    float s = fsin[tt * HD2n + d];

    const float* qp = qkv + ((size_t)(b * Tn + tt)) * N3n + h * HDn + d;
    float q1 = qp[0],    q2 = qp[HD2n];
    float k1 = qp[Cn],   k2 = qp[Cn + HD2n];

    float rq1 = (q1 * c - q2 * s) * 0.125f;
    float rq2 = (q1 * s + q2 * c) * 0.125f;
    float rk1 = k1 * c - k2 * s;
    float rk2 = k1 * s + k2 * c;

    size_t o = ((size_t)(b * Hn + h) * Tn + tt) * HDn + d;
    __nv_bfloat16 v;
    v = __float2bfloat16(rq1); Qh[o] = v;
    Ql[o] = __float2bfloat16(rq1 - __bfloat162float(v));
    v = __float2bfloat16(rq2); Qh[o + HD2n] = v;
    Ql[o + HD2n] = __float2bfloat16(rq2 - __bfloat162float(v));
    v = __float2bfloat16(rk1); Kh[o] = v;
    Kl[o] = __float2bfloat16(rk1 - __bfloat162float(v));
    v = __float2bfloat16(rk2); Kh[o + HD2n] = v;
    Kl[o + HD2n] = __float2bfloat16(rk2 - __bfloat162float(v));
}

// ---------------------------------------------------------------------------
// Prep B: V hi/lo split + transpose -> [bh][64 hd][2048 T] bf16
// ---------------------------------------------------------------------------
__global__ __launch_bounds__(256) void v_split_t_kernel(
    const float* __restrict__ qkv,
    __nv_bfloat16* __restrict__ Vh, __nv_bfloat16* __restrict__ Vl)
{
    __shared__ float vs[64][65];
    int tb = blockIdx.x, h = blockIdx.y, b = blockIdx.z;
    int tid = threadIdx.x;
    int r = tid >> 2, cq = (tid & 3) * 16;
    const float* src = qkv + ((size_t)(b * Tn + tb * 64 + r)) * N3n
                       + 2 * Cn + h * HDn + cq;
    #pragma unroll
    for (int i = 0; i < 4; i++) {
        float4 v4 = *(const float4*)(src + i * 4);
        vs[r][cq + i * 4 + 0] = v4.x;
        vs[r][cq + i * 4 + 1] = v4.y;
        vs[r][cq + i * 4 + 2] = v4.z;
        vs[r][cq + i * 4 + 3] = v4.w;
    }
    __syncthreads();
    size_t base = ((size_t)(b * Hn + h) * HDn + r) * Tn + tb * 64 + cq;
    #pragma unroll
    for (int i = 0; i < 16; i++) {
        float v = vs[cq + i][r];
        __nv_bfloat16 hv = __float2bfloat16(v);
        Vh[base + i] = hv;
        Vl[base + i] = __float2bfloat16(v - __bfloat162float(hv));
    }
}

// ---------------------------------------------------------------------------
// Flash attention via mma.sync bf16x3, ldmatrix fragment loads.
// ---------------------------------------------------------------------------
#define FSTR      144u                 // 72 bf16 per row
#define FQ_BYTES  (128u * FSTR)        // 18432
#define FK_BYTES  (64u * FSTR)         // 9216
#define FSTAGE    (4u * FK_BYTES)      // 36864
#define FA2_SMEM  (2u * FQ_BYTES + 2u * FSTAGE)   // 110592

__global__ __launch_bounds__(256) void flash_mma_kernel(
    const __nv_bfloat16* __restrict__ Qh_, const __nv_bfloat16* __restrict__ Ql_,
    const __nv_bfloat16* __restrict__ Kh_, const __nv_bfloat16* __restrict__ Kl_,
    const __nv_bfloat16* __restrict__ Vh_, const __nv_bfloat16* __restrict__ Vl_,
    __nv_bfloat16* __restrict__ ah, __nv_bfloat16* __restrict__ al)
{
    extern __shared__ unsigned char smem[];
    const uint32_t sb = smem_u32(smem);

    const int tid  = threadIdx.x;
    const int lane = tid & 31;
    const int w    = tid >> 5;
    const int g    = lane >> 2;
    const int t    = lane & 3;

    const int qb = 15 - blockIdx.x;
    const int h  = blockIdx.y;
    const int b  = blockIdx.z;
    const int bh_ = b * Hn + h;
    const size_t qk_base = (size_t)bh_ * Tn * HDn;
    const size_t v_base  = (size_t)bh_ * HDn * Tn;
    const float L2E = 1.44269504088896f;

    const uint32_t a_lane = (uint32_t)((lane & 7) + ((lane >> 3) & 1) * 8) * FSTR
                          + (uint32_t)(lane >> 4) * 16u;
    const uint32_t b_lane = (uint32_t)((lane & 7) + ((lane >> 4) & 1) * 8) * FSTR
                          + (uint32_t)((lane >> 3) & 1) * 16u;

    #pragma unroll
    for (int i = 0; i < 4; i++) {
        int u = tid + i * 256;
        int row = u >> 3, q = u & 7;
        size_t gof = qk_base + (size_t)(qb * 128 + row) * HDn + q * 8;
        CP_ASYNC16(sb + row * FSTR + q * 16u, Qh_ + gof);
        CP_ASYNC16(sb + FQ_BYTES + row * FSTR + q * 16u, Ql_ + gof);
    }
    CP_COMMIT();

    auto load_kv = [&](int kb) {
        uint32_t base = sb + 2u * FQ_BYTES + (uint32_t)(kb & 1) * FSTAGE;
        #pragma unroll
        for (int i = 0; i < 2; i++) {
            int u = tid + i * 256;
            int row = u >> 3, q = u & 7;
            size_t kof = qk_base + (size_t)(kb * 64 + row) * HDn + q * 8;
            size_t vof = v_base + (size_t)row * Tn + kb * 64 + q * 8;
            CP_ASYNC16(base + row * FSTR + q * 16u, Kh_ + kof);
            CP_ASYNC16(base + FK_BYTES + row * FSTR + q * 16u, Kl_ + kof);
            CP_ASYNC16(base + 2u * FK_BYTES + row * FSTR + q * 16u, Vh_ + vof);
            CP_ASYNC16(base + 3u * FK_BYTES + row * FSTR + q * 16u, Vl_ + vof);
        }
        CP_COMMIT();
    };

    float o[8][4];
    #pragma unroll
    for (int j = 0; j < 8; j++)
        #pragma unroll
        for (int e = 0; e < 4; e++) o[j][e] = 0.f;
    float m_i[2] = {-1e30f, -1e30f};
    float l_i[2] = {0.f, 0.f};

    const int row_hi = qb * 128 + w * 16 + 15;
    const int nkb = 2 * qb + 2;

    load_kv(0);

    for (int kb = 0; kb < nkb; kb++) {
        if (kb + 1 < nkb) {
            load_kv(kb + 1);
            asm volatile("cp.async.wait_group 1;" ::: "memory");
        } else {
            asm volatile("cp.async.wait_group 0;" ::: "memory");
        }
        __syncthreads();

        const bool active = (kb * 64 <= row_hi);
        if (active) {
            const uint32_t kbase = sb + 2u * FQ_BYTES + (uint32_t)(kb & 1) * FSTAGE;

            float s[8][4];
            #pragma unroll
            for (int j = 0; j < 8; j++)
                #pragma unroll
                for (int e = 0; e < 4; e++) s[j][e] = 0.f;

            #pragma unroll
            for (int kk = 0; kk < 4; kk++) {
                uint32_t qaddr = sb + (uint32_t)(w * 16) * FSTR + 32u * kk + a_lane;
                uint32_t aQh[4], aQl[4];
                LDSM4(aQh[0], aQh[1], aQh[2], aQh[3], qaddr);
                LDSM4(aQl[0], aQl[1], aQl[2], aQl[3], qaddr + FQ_BYTES);
                #pragma unroll
                for (int p = 0; p < 4; p++) {
                    uint32_t bKh[2][2], bKl[2][2];
                    uint32_t br = kbase + (uint32_t)(p * 16) * FSTR + 32u * kk + b_lane;
                    LDSM4(bKh[0][0], bKh[0][1], bKh[1][0], bKh[1][1], br);
                    LDSM4(bKl[0][0], bKl[0][1], bKl[1][0], bKl[1][1], br + FK_BYTES);
                    #pragma unroll
                    for (int jj = 0; jj < 2; jj++) {
                        const int j = p * 2 + jj;
                        MMA16816(s[j], aQh, bKh[jj]);
                        MMA16816(s[j], aQh, bKl[jj]);
                        MMA16816(s[j], aQl, bKh[jj]);
                    }
                }
            }

            if (kb * 64 + 63 > qb * 128 + w * 16) {
                #pragma unroll
                for (int j = 0; j < 8; j++)
                    #pragma unroll
                    for (int e = 0; e < 4; e++) {
                        int col = kb * 64 + j * 8 + 2 * t + (e & 1);
                        int row = qb * 128 + w * 16 + g + ((e >> 1) << 3);
                        if (col > row) s[j][e] = -1e30f;
                    }
            }

            #pragma unroll
            for (int u = 0; u < 2; u++) {
                float mx = -1e30f;
                #pragma unroll
                for (int j = 0; j < 8; j++)
                    mx = fmaxf(mx, fmaxf(s[j][2 * u], s[j][2 * u + 1]));
                mx = fmaxf(mx, __shfl_xor_sync(0xffffffffu, mx, 1));
                mx = fmaxf(mx, __shfl_xor_sync(0xffffffffu, mx, 2));
                float mnew  = fmaxf(m_i[u], mx);
                float alpha = exp2f((m_i[u] - mnew) * L2E);
                m_i[u] = mnew;
                float rs = 0.f;
                #pragma unroll
                for (int j = 0; j < 8; j++) {
                    float p0 = exp2f((s[j][2 * u]     - mnew) * L2E);
                    float p1 = exp2f((s[j][2 * u + 1] - mnew) * L2E);
                    s[j][2 * u] = p0; s[j][2 * u + 1] = p1;
                    rs += p0 + p1;
                }
                rs += __shfl_xor_sync(0xffffffffu, rs, 1);
                rs += __shfl_xor_sync(0xffffffffu, rs, 2);
                l_i[u] = l_i[u] * alpha + rs;
                #pragma unroll
                for (int j = 0; j < 8; j++) {
                    o[j][2 * u]     *= alpha;
                    o[j][2 * u + 1] *= alpha;
                }
            }

            const uint32_t vbase = kbase + 2u * FK_BYTES;
            #pragma unroll
            for (int kk = 0; kk < 4; kk++) {
                const int n0 = 2 * kk, n1 = 2 * kk + 1;
                uint32_t aPh[4], aPl[4];
                {
                    float p00 = s[n0][0], p01 = s[n0][1];
                    float p02 = s[n0][2], p03 = s[n0][3];
                    float p10 = s[n1][0], p11 = s[n1][1];
                    float p12 = s[n1][2], p13 = s[n1][3];
                    __nv_bfloat16 h00 = __float2bfloat16(p00);
                    __nv_bfloat16 h01 = __float2bfloat16(p01);
                    __nv_bfloat16 h02 = __float2bfloat16(p02);
                    __nv_bfloat16 h03 = __float2bfloat16(p03);
                    __nv_bfloat16 h10 = __float2bfloat16(p10);
                    __nv_bfloat16 h11 = __float2bfloat16(p11);
                    __nv_bfloat16 h12 = __float2bfloat16(p12);
                    __nv_bfloat16 h13 = __float2bfloat16(p13);
                    aPh[0] = ((uint32_t)*(uint16_t*)&h01 << 16) | *(uint16_t*)&h00;
                    aPh[1] = ((uint32_t)*(uint16_t*)&h03 << 16) | *(uint16_t*)&h02;
                    aPh[2] = ((uint32_t)*(uint16_t*)&h11 << 16) | *(uint16_t*)&h10;
                    aPh[3] = ((uint32_t)*(uint16_t*)&h13 << 16) | *(uint16_t*)&h12;
                    aPl[0] = pack_bf2(p00 - __bfloat162float(h00),
                                      p01 - __bfloat162float(h01));
                    aPl[1] = pack_bf2(p02 - __bfloat162float(h02),
                                      p03 - __bfloat162float(h03));
                    aPl[2] = pack_bf2(p10 - __bfloat162float(h10),
                                      p11 - __bfloat162float(h11));
                    aPl[3] = pack_bf2(p12 - __bfloat162float(h12),
                                      p13 - __bfloat162float(h13));
                }
                #pragma unroll
                for (int p = 0; p < 4; p++) {
                    uint32_t bVh[2][2], bVl[2][2];
                    uint32_t br = vbase + (uint32_t)(p * 16) * FSTR + 32u * kk + b_lane;
                    LDSM4(bVh[0][0], bVh[0][1], bVh[1][0], bVh[1][1], br);
                    LDSM4(bVl[0][0], bVl[0][1], bVl[1][0], bVl[1][1], br + FK_BYTES);
                    #pragma unroll
                    for (int jj = 0; jj < 2; jj++) {
                        const int j = p * 2 + jj;
                        MMA16816(o[j], aPh, bVh[jj]);
                        MMA16816(o[j], aPl, bVh[jj]);
                        MMA16816(o[j], aPh, bVl[jj]);
                    }
                }
            }
        }
        __syncthreads();
    }

    #pragma unroll
    for (int u = 0; u < 2; u++) {
        float inv = 1.0f / l_i[u];
        int row = b * Tn + qb * 128 + w * 16 + u * 8 + g;
        #pragma unroll
        for (int j = 0; j < 8; j++) {
            float p0 = o[j][2 * u] * inv;
            float p1 = o[j][2 * u + 1] * inv;
            __nv_bfloat16 h0 = __float2bfloat16(p0);
            __nv_bfloat16 h1 = __float2bfloat16(p1);
            uint32_t hi = ((uint32_t)*(uint16_t*)&h1 << 16) | *(uint16_t*)&h0;
            uint32_t lo = pack_bf2(p0 - __bfloat162float(h0),
                                   p1 - __bfloat162float(h1));
            size_t off = (size_t)row * Cn + h * HDn + j * 8 + 2 * t;
            *(uint32_t*)(ah + off) = hi;
            *(uint32_t*)(al + off) = lo;
        }
    }
}

// ---------------------------------------------------------------------------
extern "C" void kernel_launch(void* const* d_in, const int* in_sizes, int n_in,
                              void* d_out, int out_size)
{
    const float* x     = (const float*)d_in[0];
    const float* fcos  = (const float*)d_in[1];
    const float* fsin  = (const float*)d_in[2];
    const float* Wqkv  = (const float*)d_in[3];
    const float* bqkv  = (const float*)d_in[4];
    const float* Wproj = (const float*)d_in[5];
    const float* bproj = (const float*)d_in[6];
    float* out = (float*)d_out;

    unsigned char* pool = nullptr;
    cudaGetSymbolAddress((void**)&pool, g_pool);
    float* qkv = (float*)(pool + OFF_QKV);
    __nv_bfloat16* xh  = (__nv_bfloat16*)(pool + OFF_XH);
    __nv_bfloat16* xl  = (__nv_bfloat16*)(pool + OFF_XL);
    __nv_bfloat16* wqh = (__nv_bfloat16*)(pool + OFF_WQH);
    __nv_bfloat16* wql = (__nv_bfloat16*)(pool + OFF_WQL);
    __nv_bfloat16* wph = (__nv_bfloat16*)(pool + OFF_WPH);
    __nv_bfloat16* wpl = (__nv_bfloat16*)(pool + OFF_WPL);
    __nv_bfloat16* ah  = (__nv_bfloat16*)(pool + OFF_AH);
    __nv_bfloat16* al  = (__nv_bfloat16*)(pool + OFF_AL);
    __nv_bfloat16* qh  = (__nv_bfloat16*)(pool + OFF_QH);
    __nv_bfloat16* ql  = (__nv_bfloat16*)(pool + OFF_QL);
    __nv_bfloat16* kh  = (__nv_bfloat16*)(pool + OFF_KH);
    __nv_bfloat16* kl  = (__nv_bfloat16*)(pool + OFF_KL);
    __nv_bfloat16* vh  = (__nv_bfloat16*)(pool + OFF_VH);
    __nv_bfloat16* vl  = (__nv_bfloat16*)(pool + OFF_VL);

    cudaFuncSetAttribute(gemm_bf16x3_kernel,
                         cudaFuncAttributeMaxDynamicSharedMemorySize, GEMM_SMEM);
    cudaFuncSetAttribute(gemm_bf16x3_kernel,
                         cudaFuncAttributePreferredSharedMemoryCarveout, 100);
    cudaFuncSetAttribute(flash_mma_kernel,
                         cudaFuncAttributeMaxDynamicSharedMemorySize, FA2_SMEM);
    cudaFuncSetAttribute(flash_mma_kernel,
                         cudaFuncAttributePreferredSharedMemoryCarveout, 100);

    // prep
    split_kernel<<<(Mn * Cn) / 256, 256>>>(x, xh, xl, Mn * Cn);
    transpose_split_kernel<<<dim3(N3n / 32, Kn / 32), 256>>>(Wqkv, wqh, wql, Kn, N3n);
    transpose_split_kernel<<<dim3(Cn / 32, Kn / 32), 256>>>(Wproj, wph, wpl, Kn, Cn);

    // 1) qkv = x @ Wqkv + bqkv
    gemm_bf16x3_kernel<<<dim3(N3n / 128, Mn / 128), 256, GEMM_SMEM>>>(
        N3n, xh, xl, wqh, wql, bqkv, qkv);

    // 2) RoPE + split Q,K ; split+transpose V
    rope_split_qk_kernel<<<(Bn * Tn * Hn * 32) / 256, 256>>>(
        qkv, fcos, fsin, qh, ql, kh, kl);
    v_split_t_kernel<<<dim3(Tn / 64, Hn, Bn), 256>>>(qkv, vh, vl);

    // 3) flash attention (mma) -> ah/al bf16 hi/lo
    flash_mma_kernel<<<dim3(Tn / 128, Hn, Bn), 256, FA2_SMEM>>>(
        qh, ql, kh, kl, vh, vl, ah, al);

    // 4) out = att @ Wproj + bproj
    gemm_bf16x3_kernel<<<dim3(Cn / 128, Mn / 128), 256, GEMM_SMEM>>>(
        Cn, ah, al, wph, wpl, bproj, out);
}

// round 16
// speedup vs baseline: 1.0865x; 1.0865x over previous
#include <cuda_runtime.h>
#include <cuda_bf16.h>
#include <cstdint>
#include <math.h>

#define Bn   2
#define Tn   2048
#define Cn   1024
#define Hn   16
#define HDn  64
#define HD2n 32
#define Mn   (Bn * Tn)          // 4096
#define N3n  (3 * Cn)           // 3072
#define Kn   1024

// ---------------------------------------------------------------------------
// Scratch pool
// ---------------------------------------------------------------------------
#define OFF_QKV   0ull                                   // fp32 [4096][3072]
#define OFF_XH    (OFF_QKV   + 50331648ull)              // bf16 [4096][1024]
#define OFF_XL    (OFF_XH    + 8388608ull)
#define OFF_WQH   (OFF_XL    + 8388608ull)               // bf16 [3072][1024]
#define OFF_WQL   (OFF_WQH   + 6291456ull)
#define OFF_WPH   (OFF_WQL   + 6291456ull)               // bf16 [1024][1024]
#define OFF_WPL   (OFF_WPH   + 2097152ull)
#define OFF_AH    (OFF_WPL   + 2097152ull)               // bf16 [4096][1024]
#define OFF_AL    (OFF_AH    + 8388608ull)
#define OFF_QH    (OFF_AL    + 8388608ull)               // bf16 [32][2048][64]
#define OFF_QL    (OFF_QH    + 8388608ull)
#define OFF_KH    (OFF_QL    + 8388608ull)
#define OFF_KL    (OFF_KH    + 8388608ull)
#define OFF_VH    (OFF_KL    + 8388608ull)               // bf16 [32][64][2048]
#define OFF_VL    (OFF_VH    + 8388608ull)
#define POOL_SZ   (OFF_VL    + 8388608ull)

__device__ __align__(1024) unsigned char g_pool[POOL_SZ];

// ---------------------------------------------------------------------------
// helpers
// ---------------------------------------------------------------------------
#define MMA16816(d, a, b) \
    asm volatile( \
        "mma.sync.aligned.m16n8k16.row.col.f32.bf16.bf16.f32 " \
        "{%0,%1,%2,%3}, {%4,%5,%6,%7}, {%8,%9}, {%0,%1,%2,%3};" \
        : "+f"((d)[0]), "+f"((d)[1]), "+f"((d)[2]), "+f"((d)[3]) \
        : "r"((a)[0]), "r"((a)[1]), "r"((a)[2]), "r"((a)[3]), \
          "r"((b)[0]), "r"((b)[1]))

#define LDSM4(r0, r1, r2, r3, a) \
    asm volatile("ldmatrix.sync.aligned.m8n8.x4.shared.b16 {%0,%1,%2,%3}, [%4];" \
        : "=r"(r0), "=r"(r1), "=r"(r2), "=r"(r3) : "r"(a))

#define CP_ASYNC16(dst, src) \
    asm volatile("cp.async.cg.shared.global [%0], [%1], 16;" \
                 :: "r"(dst), "l"(src) : "memory")
#define CP_COMMIT() asm volatile("cp.async.commit_group;" ::: "memory")

__device__ __forceinline__ uint32_t smem_u32(const void* p) {
    uint32_t a;
    asm("{ .reg .u64 t; cvta.to.shared.u64 t, %1; cvt.u32.u64 %0, t; }"
        : "=r"(a) : "l"(p));
    return a;
}

__device__ __forceinline__ uint32_t pack_bf2(float x, float y) {
    __nv_bfloat162 v = __floats2bfloat162_rn(x, y);
    return *(uint32_t*)&v;
}

// ---------------------------------------------------------------------------
// Split fp32 -> bf16 hi/lo
// ---------------------------------------------------------------------------
__global__ __launch_bounds__(256) void split_kernel(
    const float* __restrict__ in, __nv_bfloat16* __restrict__ h,
    __nv_bfloat16* __restrict__ l, int n)
{
    int i = blockIdx.x * 256 + threadIdx.x;
    if (i < n) {
        float v = in[i];
        __nv_bfloat16 hv = __float2bfloat16(v);
        h[i] = hv;
        l[i] = __float2bfloat16(v - __bfloat162float(hv));
    }
}

// ---------------------------------------------------------------------------
// Transpose + split: W[K][N] fp32 -> Th, Tl [N][K] bf16
// ---------------------------------------------------------------------------
__global__ __launch_bounds__(256) void transpose_split_kernel(
    const float* __restrict__ W, __nv_bfloat16* __restrict__ Th,
    __nv_bfloat16* __restrict__ Tl, int K, int N)
{
    __shared__ float t[32][33];
    int n0 = blockIdx.x * 32, k0 = blockIdx.y * 32;
    int tx = threadIdx.x & 31, ty = threadIdx.x >> 5;
    #pragma unroll
    for (int r = 0; r < 4; r++)
        t[ty + 8 * r][tx] = W[(size_t)(k0 + ty + 8 * r) * N + n0 + tx];
    __syncthreads();
    #pragma unroll
    for (int r = 0; r < 4; r++) {
        float v = t[tx][ty + 8 * r];
        __nv_bfloat16 hv = __float2bfloat16(v);
        size_t o = (size_t)(n0 + ty + 8 * r) * K + k0 + tx;
        Th[o] = hv;
        Tl[o] = __float2bfloat16(v - __bfloat162float(hv));
    }
}

// ---------------------------------------------------------------------------
// bf16x3 GEMM (exact R8 config: 2-stage, 2 CTAs/SM, term-major)
// ---------------------------------------------------------------------------
#define GSTRIDE  80u
#define GMATB    10240u
#define GSTAGE   40960u
#define GEMM_SMEM (2 * GSTAGE)
#define NCHUNK   32

__global__ __launch_bounds__(256, 2) void gemm_bf16x3_kernel(int N,
    const __nv_bfloat16* __restrict__ Ah, const __nv_bfloat16* __restrict__ Al,
    const __nv_bfloat16* __restrict__ Bh, const __nv_bfloat16* __restrict__ Bl,
    const float* __restrict__ bias, float* __restrict__ C)
{
    extern __shared__ unsigned char smem[];
    const uint32_t sb = smem_u32(smem);

    const int tid  = threadIdx.x;
    const int lane = tid & 31;
    const int warp = tid >> 5;
    const int wm   = warp >> 2;
    const int wn   = warp & 3;
    const int g    = lane >> 2;
    const int t    = lane & 3;
    const int brow = blockIdx.y * 128;
    const int bcol = blockIdx.x * 128;

    const uint32_t a_lane = (uint32_t)((lane & 7) + ((lane >> 3) & 1) * 8) * GSTRIDE
                          + (uint32_t)(lane >> 4) * 16u;
    const uint32_t b_lane = (uint32_t)((lane & 7) + ((lane >> 4) & 1) * 8) * GSTRIDE
                          + (uint32_t)((lane >> 3) & 1) * 16u;

    float acc[4][4][4];
    #pragma unroll
    for (int i = 0; i < 4; i++)
        #pragma unroll
        for (int j = 0; j < 4; j++)
            #pragma unroll
            for (int r = 0; r < 4; r++) acc[i][j][r] = 0.f;

    auto load_chunk = [&](int c) {
        const uint32_t base = sb + (uint32_t)(c & 1) * GSTAGE;
        const int kc = c * 32;
        #pragma unroll
        for (int m = 0; m < 4; m++) {
            const __nv_bfloat16* src = (m == 0) ? Ah : (m == 1) ? Al
                                     : (m == 2) ? Bh : Bl;
            const int rb = (m < 2) ? brow : bcol;
            #pragma unroll
            for (int i = 0; i < 2; i++) {
                int u   = tid + i * 256;
                int row = u >> 2, q = u & 3;
                const __nv_bfloat16* gsrc =
                    src + (size_t)(rb + row) * Kn + kc + q * 8;
                uint32_t dst = base + m * GMATB + row * GSTRIDE + q * 16u;
                CP_ASYNC16(dst, gsrc);
            }
        }
        CP_COMMIT();
    };

    load_chunk(0);
    load_chunk(1);

    for (int c = 0; c < NCHUNK; c++) {
        if (c < NCHUNK - 1)
            asm volatile("cp.async.wait_group 1;" ::: "memory");
        else
            asm volatile("cp.async.wait_group 0;" ::: "memory");
        __syncthreads();

        const uint32_t stg = sb + (uint32_t)(c & 1) * GSTAGE;

        #pragma unroll
        for (int s = 0; s < 2; s++) {
            const uint32_t kb = s * 32u;
            uint32_t ah[4][4], al[4][4];
            #pragma unroll
            for (int i = 0; i < 4; i++) {
                uint32_t r = stg + (uint32_t)(wm * 64 + i * 16) * GSTRIDE + kb + a_lane;
                LDSM4(ah[i][0], ah[i][1], ah[i][2], ah[i][3], r);
                LDSM4(al[i][0], al[i][1], al[i][2], al[i][3], r + GMATB);
            }
            #pragma unroll
            for (int p = 0; p < 2; p++) {
                uint32_t bh[2][2], bl[2][2];
                uint32_t r = stg + 2u * GMATB
                           + (uint32_t)(wn * 32 + p * 16) * GSTRIDE + kb + b_lane;
                LDSM4(bh[0][0], bh[0][1], bh[1][0], bh[1][1], r);
                LDSM4(bl[0][0], bl[0][1], bl[1][0], bl[1][1], r + GMATB);
                #pragma unroll
                for (int jj = 0; jj < 2; jj++) {
                    const int j = p * 2 + jj;
                    #pragma unroll
                    for (int i = 0; i < 4; i++) MMA16816(acc[i][j], ah[i], bh[jj]);
                    #pragma unroll
                    for (int i = 0; i < 4; i++) MMA16816(acc[i][j], ah[i], bl[jj]);
                    #pragma unroll
                    for (int i = 0; i < 4; i++) MMA16816(acc[i][j], al[i], bh[jj]);
                }
            }
        }
        __syncthreads();
        if (c + 2 < NCHUNK) load_chunk(c + 2);
    }

    #pragma unroll
    for (int i = 0; i < 4; i++) {
        const int r0 = brow + wm * 64 + i * 16 + g;
        #pragma unroll
        for (int j = 0; j < 4; j++) {
            const int col = bcol + wn * 32 + j * 8 + t * 2;
            float2 bs = *(const float2*)(bias + col);
            float2 o0, o1;
            o0.x = acc[i][j][0] + bs.x;
            o0.y = acc[i][j][1] + bs.y;
            o1.x = acc[i][j][2] + bs.x;
            o1.y = acc[i][j][3] + bs.y;
            *(float2*)(C + (size_t)r0 * N + col)       = o0;
            *(float2*)(C + (size_t)(r0 + 8) * N + col) = o1;
        }
    }
}

// ---------------------------------------------------------------------------
// Prep A: RoPE + scale(Q) + hi/lo split of Q,K -> [bh][T][64] bf16
// ---------------------------------------------------------------------------
__global__ __launch_bounds__(256) void rope_split_qk_kernel(
    const float* __restrict__ qkv,
    const float* __restrict__ fcos, const float* __restrict__ fsin,
    __nv_bfloat16* __restrict__ Qh, __nv_bfloat16* __restrict__ Ql,
    __nv_bfloat16* __restrict__ Kh, __nv_bfloat16* __restrict__ Kl)
{
    int i = blockIdx.x * 256 + threadIdx.x;
    int d  = i & 31;
    int h  = (i >> 5) & 15;
    int tt = (i >> 9) & 2047;
    int b  = i >> 20;

    float c = fcos[tt * HD2n + d];
    float s = fsin[tt * HD2n + d];

    const float* qp = qkv + ((size_t)(b * Tn + tt)) * N3n + h * HDn + d;
    float q1 = qp[0],    q2 = qp[HD2n];
    float k1 = qp[Cn],   k2 = qp[Cn + HD2n];

    float rq1 = (q1 * c - q2 * s) * 0.125f;
    float rq2 = (q1 * s + q2 * c) * 0.125f;
    float rk1 = k1 * c - k2 * s;
    float rk2 = k1 * s + k2 * c;

    size_t o = ((size_t)(b * Hn + h) * Tn + tt) * HDn + d;
    __nv_bfloat16 v;
    v = __float2bfloat16(rq1); Qh[o] = v;
    Ql[o] = __float2bfloat16(rq1 - __bfloat162float(v));
    v = __float2bfloat16(rq2); Qh[o + HD2n] = v;
    Ql[o + HD2n] = __float2bfloat16(rq2 - __bfloat162float(v));
    v = __float2bfloat16(rk1); Kh[o] = v;
    Kl[o] = __float2bfloat16(rk1 - __bfloat162float(v));
    v = __float2bfloat16(rk2); Kh[o + HD2n] = v;
    Kl[o + HD2n] = __float2bfloat16(rk2 - __bfloat162float(v));
}

// ---------------------------------------------------------------------------
// Prep B: V hi/lo split + transpose -> [bh][64 hd][2048 T] bf16
// ---------------------------------------------------------------------------
__global__ __launch_bounds__(256) void v_split_t_kernel(
    const float* __restrict__ qkv,
    __nv_bfloat16* __restrict__ Vh, __nv_bfloat16* __restrict__ Vl)
{
    __shared__ float vs[64][65];
    int tb = blockIdx.x, h = blockIdx.y, b = blockIdx.z;
    int tid = threadIdx.x;
    int r = tid >> 2, cq = (tid & 3) * 16;
    const float* src = qkv + ((size_t)(b * Tn + tb * 64 + r)) * N3n
                       + 2 * Cn + h * HDn + cq;
    #pragma unroll
    for (int i = 0; i < 4; i++) {
        float4 v4 = *(const float4*)(src + i * 4);
        vs[r][cq + i * 4 + 0] = v4.x;
        vs[r][cq + i * 4 + 1] = v4.y;
        vs[r][cq + i * 4 + 2] = v4.z;
        vs[r][cq + i * 4 + 3] = v4.w;
    }
    __syncthreads();
    size_t base = ((size_t)(b * Hn + h) * HDn + r) * Tn + tb * 64 + cq;
    #pragma unroll
    for (int i = 0; i < 16; i++) {
        float v = vs[cq + i][r];
        __nv_bfloat16 hv = __float2bfloat16(v);
        Vh[base + i] = hv;
        Vl[base + i] = __float2bfloat16(v - __bfloat162float(hv));
    }
}

// ---------------------------------------------------------------------------
// Flash attention via mma.sync bf16x3; Q fragments hoisted out of the kb loop.
// ---------------------------------------------------------------------------
#define FSTR      144u                 // 72 bf16 per row
#define FQ_BYTES  (128u * FSTR)        // 18432
#define FK_BYTES  (64u * FSTR)         // 9216
#define FSTAGE    (4u * FK_BYTES)      // 36864
#define FA2_SMEM  (2u * FQ_BYTES + 2u * FSTAGE)   // 110592

__global__ __launch_bounds__(256) void flash_mma_kernel(
    const __nv_bfloat16* __restrict__ Qh_, const __nv_bfloat16* __restrict__ Ql_,
    const __nv_bfloat16* __restrict__ Kh_, const __nv_bfloat16* __restrict__ Kl_,
    const __nv_bfloat16* __restrict__ Vh_, const __nv_bfloat16* __restrict__ Vl_,
    __nv_bfloat16* __restrict__ ah, __nv_bfloat16* __restrict__ al)
{
    extern __shared__ unsigned char smem[];
    const uint32_t sb = smem_u32(smem);

    const int tid  = threadIdx.x;
    const int lane = tid & 31;
    const int w    = tid >> 5;
    const int g    = lane >> 2;
    const int t    = lane & 3;

    const int qb = 15 - blockIdx.x;
    const int h  = blockIdx.y;
    const int b  = blockIdx.z;
    const int bh_ = b * Hn + h;
    const size_t qk_base = (size_t)bh_ * Tn * HDn;
    const size_t v_base  = (size_t)bh_ * HDn * Tn;
    const float L2E = 1.44269504088896f;

    const uint32_t a_lane = (uint32_t)((lane & 7) + ((lane >> 3) & 1) * 8) * FSTR
                          + (uint32_t)(lane >> 4) * 16u;
    const uint32_t b_lane = (uint32_t)((lane & 7) + ((lane >> 4) & 1) * 8) * FSTR
                          + (uint32_t)((lane >> 3) & 1) * 16u;

    // Q tile loads (group 0)
    #pragma unroll
    for (int i = 0; i < 4; i++) {
        int u = tid + i * 256;
        int row = u >> 3, q = u & 7;
        size_t gof = qk_base + (size_t)(qb * 128 + row) * HDn + q * 8;
        CP_ASYNC16(sb + row * FSTR + q * 16u, Qh_ + gof);
        CP_ASYNC16(sb + FQ_BYTES + row * FSTR + q * 16u, Ql_ + gof);
    }
    CP_COMMIT();

    auto load_kv = [&](int kb) {
        uint32_t base = sb + 2u * FQ_BYTES + (uint32_t)(kb & 1) * FSTAGE;
        #pragma unroll
        for (int i = 0; i < 2; i++) {
            int u = tid + i * 256;
            int row = u >> 3, q = u & 7;
            size_t kof = qk_base + (size_t)(kb * 64 + row) * HDn + q * 8;
            size_t vof = v_base + (size_t)row * Tn + kb * 64 + q * 8;
            CP_ASYNC16(base + row * FSTR + q * 16u, Kh_ + kof);
            CP_ASYNC16(base + FK_BYTES + row * FSTR + q * 16u, Kl_ + kof);
            CP_ASYNC16(base + 2u * FK_BYTES + row * FSTR + q * 16u, Vh_ + vof);
            CP_ASYNC16(base + 3u * FK_BYTES + row * FSTR + q * 16u, Vl_ + vof);
        }
        CP_COMMIT();
    };

    load_kv(0);                                       // group 1
    asm volatile("cp.async.wait_group 1;" ::: "memory");   // Q (group 0) done
    __syncthreads();

    // ---- hoist Q fragments out of the kb loop (invariant) ----
    uint32_t aQh[4][4], aQl[4][4];
    #pragma unroll
    for (int kk = 0; kk < 4; kk++) {
        uint32_t qaddr = sb + (uint32_t)(w * 16) * FSTR + 32u * kk + a_lane;
        LDSM4(aQh[kk][0], aQh[kk][1], aQh[kk][2], aQh[kk][3], qaddr);
        LDSM4(aQl[kk][0], aQl[kk][1], aQl[kk][2], aQl[kk][3], qaddr + FQ_BYTES);
    }

    float o[8][4];
    #pragma unroll
    for (int j = 0; j < 8; j++)
        #pragma unroll
        for (int e = 0; e < 4; e++) o[j][e] = 0.f;
    float m_i[2] = {-1e30f, -1e30f};
    float l_i[2] = {0.f, 0.f};

    const int row_hi = qb * 128 + w * 16 + 15;
    const int nkb = 2 * qb + 2;

    for (int kb = 0; kb < nkb; kb++) {
        if (kb + 1 < nkb) {
            load_kv(kb + 1);
            asm volatile("cp.async.wait_group 1;" ::: "memory");
        } else {
            asm volatile("cp.async.wait_group 0;" ::: "memory");
        }
        __syncthreads();

        const bool active = (kb * 64 <= row_hi);
        if (active) {
            const uint32_t kbase = sb + 2u * FQ_BYTES + (uint32_t)(kb & 1) * FSTAGE;

            float s[8][4];
            #pragma unroll
            for (int j = 0; j < 8; j++)
                #pragma unroll
                for (int e = 0; e < 4; e++) s[j][e] = 0.f;

            #pragma unroll
            for (int kk = 0; kk < 4; kk++) {
                #pragma unroll
                for (int p = 0; p < 4; p++) {
                    uint32_t bKh[2][2], bKl[2][2];
                    uint32_t br = kbase + (uint32_t)(p * 16) * FSTR + 32u * kk + b_lane;
                    LDSM4(bKh[0][0], bKh[0][1], bKh[1][0], bKh[1][1], br);
                    LDSM4(bKl[0][0], bKl[0][1], bKl[1][0], bKl[1][1], br + FK_BYTES);
                    #pragma unroll
                    for (int jj = 0; jj < 2; jj++) {
                        const int j = p * 2 + jj;
                        MMA16816(s[j], aQh[kk], bKh[jj]);
                        MMA16816(s[j], aQh[kk], bKl[jj]);
                        MMA16816(s[j], aQl[kk], bKh[jj]);
                    }
                }
            }

            if (kb * 64 + 63 > qb * 128 + w * 16) {
                #pragma unroll
                for (int j = 0; j < 8; j++)
                    #pragma unroll
                    for (int e = 0; e < 4; e++) {
                        int col = kb * 64 + j * 8 + 2 * t + (e & 1);
                        int row = qb * 128 + w * 16 + g + ((e >> 1) << 3);
                        if (col > row) s[j][e] = -1e30f;
                    }
            }

            #pragma unroll
            for (int u = 0; u < 2; u++) {
                float mx = -1e30f;
                #pragma unroll
                for (int j = 0; j < 8; j++)
                    mx = fmaxf(mx, fmaxf(s[j][2 * u], s[j][2 * u + 1]));
                mx = fmaxf(mx, __shfl_xor_sync(0xffffffffu, mx, 1));
                mx = fmaxf(mx, __shfl_xor_sync(0xffffffffu, mx, 2));
                float mnew  = fmaxf(m_i[u], mx);
                float alpha = exp2f((m_i[u] - mnew) * L2E);
                m_i[u] = mnew;
                float rs = 0.f;
                #pragma unroll
                for (int j = 0; j < 8; j++) {
                    float p0 = exp2f((s[j][2 * u]     - mnew) * L2E);
                    float p1 = exp2f((s[j][2 * u + 1] - mnew) * L2E);
                    s[j][2 * u] = p0; s[j][2 * u + 1] = p1;
                    rs += p0 + p1;
                }
                rs += __shfl_xor_sync(0xffffffffu, rs, 1);
                rs += __shfl_xor_sync(0xffffffffu, rs, 2);
                l_i[u] = l_i[u] * alpha + rs;
                #pragma unroll
                for (int j = 0; j < 8; j++) {
                    o[j][2 * u]     *= alpha;
                    o[j][2 * u + 1] *= alpha;
                }
            }

            const uint32_t vbase = kbase + 2u * FK_BYTES;
            #pragma unroll
            for (int kk = 0; kk < 4; kk++) {
                const int n0 = 2 * kk, n1 = 2 * kk + 1;
                uint32_t aPh[4], aPl[4];
                {
                    float p00 = s[n0][0], p01 = s[n0][1];
                    float p02 = s[n0][2], p03 = s[n0][3];
                    float p10 = s[n1][0], p11 = s[n1][1];
                    float p12 = s[n1][2], p13 = s[n1][3];
                    __nv_bfloat16 h00 = __float2bfloat16(p00);
                    __nv_bfloat16 h01 = __float2bfloat16(p01);
                    __nv_bfloat16 h02 = __float2bfloat16(p02);
                    __nv_bfloat16 h03 = __float2bfloat16(p03);
                    __nv_bfloat16 h10 = __float2bfloat16(p10);
                    __nv_bfloat16 h11 = __float2bfloat16(p11);
                    __nv_bfloat16 h12 = __float2bfloat16(p12);
                    __nv_bfloat16 h13 = __float2bfloat16(p13);
                    aPh[0] = ((uint32_t)*(uint16_t*)&h01 << 16) | *(uint16_t*)&h00;
                    aPh[1] = ((uint32_t)*(uint16_t*)&h03 << 16) | *(uint16_t*)&h02;
                    aPh[2] = ((uint32_t)*(uint16_t*)&h11 << 16) | *(uint16_t*)&h10;
                    aPh[3] = ((uint32_t)*(uint16_t*)&h13 << 16) | *(uint16_t*)&h12;
                    aPl[0] = pack_bf2(p00 - __bfloat162float(h00),
                                      p01 - __bfloat162float(h01));
                    aPl[1] = pack_bf2(p02 - __bfloat162float(h02),
                                      p03 - __bfloat162float(h03));
                    aPl[2] = pack_bf2(p10 - __bfloat162float(h10),
                                      p11 - __bfloat162float(h11));
                    aPl[3] = pack_bf2(p12 - __bfloat162float(h12),
                                      p13 - __bfloat162float(h13));
                }
                #pragma unroll
                for (int p = 0; p < 4; p++) {
                    uint32_t bVh[2][2], bVl[2][2];
                    uint32_t br = vbase + (uint32_t)(p * 16) * FSTR + 32u * kk + b_lane;
                    LDSM4(bVh[0][0], bVh[0][1], bVh[1][0], bVh[1][1], br);
                    LDSM4(bVl[0][0], bVl[0][1], bVl[1][0], bVl[1][1], br + FK_BYTES);
                    #pragma unroll
                    for (int jj = 0; jj < 2; jj++) {
                        const int j = p * 2 + jj;
                        MMA16816(o[j], aPh, bVh[jj]);
                        MMA16816(o[j], aPl, bVh[jj]);
                        MMA16816(o[j], aPh, bVl[jj]);
                    }
                }
            }
        }
        __syncthreads();
    }

    #pragma unroll
    for (int u = 0; u < 2; u++) {
        float inv = 1.0f / l_i[u];
        int row = b * Tn + qb * 128 + w * 16 + u * 8 + g;
        #pragma unroll
        for (int j = 0; j < 8; j++) {
            float p0 = o[j][2 * u] * inv;
            float p1 = o[j][2 * u + 1] * inv;
            __nv_bfloat16 h0 = __float2bfloat16(p0);
            __nv_bfloat16 h1 = __float2bfloat16(p1);
            uint32_t hi = ((uint32_t)*(uint16_t*)&h1 << 16) | *(uint16_t*)&h0;
            uint32_t lo = pack_bf2(p0 - __bfloat162float(h0),
                                   p1 - __bfloat162float(h1));
            size_t off = (size_t)row * Cn + h * HDn + j * 8 + 2 * t;
            *(uint32_t*)(ah + off) = hi;
            *(uint32_t*)(al + off) = lo;
        }
    }
}

// ---------------------------------------------------------------------------
extern "C" void kernel_launch(void* const* d_in, const int* in_sizes, int n_in,
                              void* d_out, int out_size)
{
    const float* x     = (const float*)d_in[0];
    const float* fcos  = (const float*)d_in[1];
    const float* fsin  = (const float*)d_in[2];
    const float* Wqkv  = (const float*)d_in[3];
    const float* bqkv  = (const float*)d_in[4];
    const float* Wproj = (const float*)d_in[5];
    const float* bproj = (const float*)d_in[6];
    float* out = (float*)d_out;

    unsigned char* pool = nullptr;
    cudaGetSymbolAddress((void**)&pool, g_pool);
    float* qkv = (float*)(pool + OFF_QKV);
    __nv_bfloat16* xh  = (__nv_bfloat16*)(pool + OFF_XH);
    __nv_bfloat16* xl  = (__nv_bfloat16*)(pool + OFF_XL);
    __nv_bfloat16* wqh = (__nv_bfloat16*)(pool + OFF_WQH);
    __nv_bfloat16* wql = (__nv_bfloat16*)(pool + OFF_WQL);
    __nv_bfloat16* wph = (__nv_bfloat16*)(pool + OFF_WPH);
    __nv_bfloat16* wpl = (__nv_bfloat16*)(pool + OFF_WPL);
    __nv_bfloat16* ah  = (__nv_bfloat16*)(pool + OFF_AH);
    __nv_bfloat16* al  = (__nv_bfloat16*)(pool + OFF_AL);
    __nv_bfloat16* qh  = (__nv_bfloat16*)(pool + OFF_QH);
    __nv_bfloat16* ql  = (__nv_bfloat16*)(pool + OFF_QL);
    __nv_bfloat16* kh  = (__nv_bfloat16*)(pool + OFF_KH);
    __nv_bfloat16* kl  = (__nv_bfloat16*)(pool + OFF_KL);
    __nv_bfloat16* vh  = (__nv_bfloat16*)(pool + OFF_VH);
    __nv_bfloat16* vl  = (__nv_bfloat16*)(pool + OFF_VL);

    cudaFuncSetAttribute(gemm_bf16x3_kernel,
                         cudaFuncAttributeMaxDynamicSharedMemorySize, GEMM_SMEM);
    cudaFuncSetAttribute(gemm_bf16x3_kernel,
                         cudaFuncAttributePreferredSharedMemoryCarveout, 100);
    cudaFuncSetAttribute(flash_mma_kernel,
                         cudaFuncAttributeMaxDynamicSharedMemorySize, FA2_SMEM);
    cudaFuncSetAttribute(flash_mma_kernel,
                         cudaFuncAttributePreferredSharedMemoryCarveout, 100);

    // prep
    split_kernel<<<(Mn * Cn) / 256, 256>>>(x, xh, xl, Mn * Cn);
    transpose_split_kernel<<<dim3(N3n / 32, Kn / 32), 256>>>(Wqkv, wqh, wql, Kn, N3n);
    transpose_split_kernel<<<dim3(Cn / 32, Kn / 32), 256>>>(Wproj, wph, wpl, Kn, Cn);

    // 1) qkv = x @ Wqkv + bqkv
    gemm_bf16x3_kernel<<<dim3(N3n / 128, Mn / 128), 256, GEMM_SMEM>>>(
        N3n, xh, xl, wqh, wql, bqkv, qkv);

    // 2) RoPE + split Q,K ; split+transpose V
    rope_split_qk_kernel<<<(Bn * Tn * Hn * 32) / 256, 256>>>(
        qkv, fcos, fsin, qh, ql, kh, kl);
    v_split_t_kernel<<<dim3(Tn / 64, Hn, Bn), 256>>>(qkv, vh, vl);

    // 3) flash attention (mma) -> ah/al bf16 hi/lo
    flash_mma_kernel<<<dim3(Tn / 128, Hn, Bn), 256, FA2_SMEM>>>(
        qh, ql, kh, kl, vh, vl, ah, al);

    // 4) out = att @ Wproj + bproj
    gemm_bf16x3_kernel<<<dim3(Cn / 128, Mn / 128), 256, GEMM_SMEM>>>(
        Cn, ah, al, wph, wpl, bproj, out);
}